// round 9
// baseline (speedup 1.0000x reference)
#include <cuda_runtime.h>

// Truncated path signature, D=6, depth K=4, L=65536 points (65535 increments).
// Output: [S1(6), S2(36), S3(216), S4(1296)] = 1554 floats.
//
// Stage A: 592 chunks x 111 steps. Each chunk handled by 36 threads; thread owns
//          prefix ab: S2[ab], S3[ab,*], S4[ab,*,*], and tracks scalar S1[a].
//          Per-step Horner update, no intra-step synchronization.
// Stage B: Chen-product folds: 592 -> 148 -> 8 -> 1 (three launches).

#define DD 6
#define NPTS 65536
#define NINC 65535
#define NCHUNK 592
#define SPC 111          // steps per chunk (592*111 = 65712 >= 65535, zero-padded)
#define CPB 4            // chunks per block
#define BLOCKS_A (NCHUNK / CPB)      // 148
#define THREADS_A (CPB * 36)         // 144
#define SIG 1554
#define O2 6
#define O3 42
#define O4 258

__device__ float g_sigA[NCHUNK * SIG];   // 3.7 MB scratch
__device__ float g_sigB[148 * SIG];
__device__ float g_sigC[8 * SIG];

// ---------------------------------------------------------------------------
// Stage A: per-chunk sequential signature via Horner-factored exp step.
//   exp(v): e_k = v^{(x)k}/k!
//   S4 += ((S3 + ((S2 + ((S1 + v/4) (x) v/3)) (x) v/2)) (x) v)
//   S3 += ((S2 + ((S1 + v/3) (x) v/2)) (x) v)
//   S2 += ((S1 + v/2) (x) v)
//   S1 += v
// ---------------------------------------------------------------------------
__global__ __launch_bounds__(THREADS_A) void stageA_kernel(const float* __restrict__ x)
{
    // per-step slot of 16 floats: [v0..v5, pad, pad, v/2 (6), pad, pad]
    __shared__ __align__(16) float sv[CPB * SPC * 16];

    const int tid = threadIdx.x;
    const long blkIncBase = (long)blockIdx.x * (CPB * SPC);

    // precompute increments v and v/2 into shared (coalesced global reads)
    for (int idx = tid; idx < CPB * SPC * DD; idx += THREADS_A) {
        int s = idx / DD;
        int j = idx - s * DD;
        long g = blkIncBase + s;          // global increment index
        float v = 0.0f;
        if (g < (long)NINC)
            v = x[(g + 1) * DD + j] - x[g * DD + j];
        sv[s * 16 + j]     = v;
        sv[s * 16 + 8 + j] = 0.5f * v;
    }
    __syncthreads();

    const int lc = tid / 36;              // local chunk 0..3
    const int ab = tid - lc * 36;         // owned (a,b) prefix
    const int a  = ab / 6;
    const int b  = ab - a * 6;

    float s1 = 0.0f;                      // S1[a] (replicated across b)
    float s2 = 0.0f;                      // S2[ab]
    float s3[6];                          // S3[ab,c]
    float s4[36];                         // S4[ab,c,d]
#pragma unroll
    for (int c = 0; c < 6; c++) s3[c] = 0.0f;
#pragma unroll
    for (int k = 0; k < 36; k++) s4[k] = 0.0f;

    const float* base = &sv[lc * SPC * 16];
    const float THIRD = 1.0f / 3.0f;

#pragma unroll 1
    for (int t = 0; t < SPC; t++) {
        const float* p = base + t * 16;
        const float4* q = (const float4*)p;
        float4 f0 = q[0], f1 = q[1], f2 = q[2], f3 = q[3];
        float vv[6] = { f0.x, f0.y, f0.z, f0.w, f1.x, f1.y };   // v
        float hv[6] = { f2.x, f2.y, f2.z, f2.w, f3.x, f3.y };   // v/2

        // per-thread scalars at runtime indices a,b -> fetch from shared
        float vA = p[a],     vB = p[b];
        float hA = p[8 + a], hB = p[8 + b];
        float tA = vA * THIRD, tB = vB * THIRD;

        // Horner chains (all reads of s1,s2,s3 are pre-update values)
        float V1 = fmaf(vA, 0.25f, s1);
        float V2 = fmaf(V1, tB, s2);
        float W1 = s1 + tA;
        float W2 = fmaf(W1, hB, s2);
        float U1 = s1 + hA;
        s2 = fmaf(U1, vB, s2);
        s1 += vA;

#pragma unroll
        for (int c = 0; c < 6; c++) {
            float V3 = fmaf(V2, hv[c], s3[c]);     // uses old s3
            s3[c]    = fmaf(W2, vv[c], s3[c]);
#pragma unroll
            for (int d = 0; d < 6; d++)
                s4[c * 6 + d] = fmaf(V3, vv[d], s4[c * 6 + d]);
        }
    }

    // write chunk signature
    const int chunk = blockIdx.x * CPB + lc;
    float* o = g_sigA + (long)chunk * SIG;
    if (b == 0) o[a] = s1;
    o[O2 + ab] = s2;
#pragma unroll
    for (int c = 0; c < 6; c++) o[O3 + ab * 6 + c] = s3[c];
#pragma unroll
    for (int k = 0; k < 36; k++) o[O4 + ab * 36 + k] = s4[k];
}

// ---------------------------------------------------------------------------
// Stage B: left-fold Chen products over a contiguous group of signatures.
//   C1 = A1+B1
//   C2 = A2+B2 + A1(x)B1
//   C3 = A3+B3 + A1(x)B2 + A2(x)B1
//   C4 = A4+B4 + A1(x)B3 + A2(x)B2 + A3(x)B1
// ---------------------------------------------------------------------------
__device__ __forceinline__ void merge_fold_body(
    const float* __restrict__ in, float* __restrict__ out, int group, int nIn)
{
    __shared__ float S[SIG];
    __shared__ float E[SIG];
    const int tid = threadIdx.x;
    const int lo = blockIdx.x * group;
    const int hi = (lo + group < nIn) ? (lo + group) : nIn;

    for (int k = tid; k < SIG; k += 256) S[k] = in[(long)lo * SIG + k];
    __syncthreads();

    for (int i = lo + 1; i < hi; i++) {
        for (int k = tid; k < SIG; k += 256) E[k] = in[(long)i * SIG + k];
        __syncthreads();

        float nv[7];
        int cnt = 0;
        for (int e = tid; e < SIG; e += 256, cnt++) {
            float r = S[e] + E[e];
            if (e >= O4) {                 // level 4
                int m = e - O4;            // a*216 + b*36 + c*6 + d
                r = fmaf(S[m / 216],      E[O3 + m % 216], r);   // A1 x B3
                r = fmaf(S[O2 + m / 36],  E[O2 + m % 36],  r);   // A2 x B2
                r = fmaf(S[O3 + m / 6],   E[m % 6],        r);   // A3 x B1
            } else if (e >= O3) {          // level 3
                int m = e - O3;            // a*36 + b*6 + c
                r = fmaf(S[m / 36],       E[O2 + m % 36],  r);   // A1 x B2
                r = fmaf(S[O2 + m / 6],   E[m % 6],        r);   // A2 x B1
            } else if (e >= O2) {          // level 2
                int m = e - O2;            // a*6 + b
                r = fmaf(S[m / 6],        E[m % 6],        r);   // A1 x B1
            }
            nv[cnt] = r;
        }
        __syncthreads();
        cnt = 0;
        for (int e = tid; e < SIG; e += 256, cnt++) S[e] = nv[cnt];
        __syncthreads();
    }

    for (int k = tid; k < SIG; k += 256) out[(long)blockIdx.x * SIG + k] = S[k];
}

__global__ __launch_bounds__(256) void merge1_kernel()            // 592 -> 148
{
    merge_fold_body(g_sigA, g_sigB, 4, NCHUNK);
}
__global__ __launch_bounds__(256) void merge2_kernel()            // 148 -> 8
{
    merge_fold_body(g_sigB, g_sigC, 19, 148);
}
__global__ __launch_bounds__(256) void merge3_kernel(float* __restrict__ out)  // 8 -> 1
{
    merge_fold_body(g_sigC, out, 8, 8);
}

// ---------------------------------------------------------------------------
extern "C" void kernel_launch(void* const* d_in, const int* in_sizes, int n_in,
                              void* d_out, int out_size)
{
    const float* x = (const float*)d_in[0];
    float* out = (float*)d_out;
    (void)in_sizes; (void)n_in; (void)out_size;

    stageA_kernel<<<BLOCKS_A, THREADS_A>>>(x);
    merge1_kernel<<<148, 256>>>();
    merge2_kernel<<<8, 256>>>();
    merge3_kernel<<<1, 256>>>(out);
}

// round 11
// speedup vs baseline: 2.6157x; 2.6157x over previous
#include <cuda_runtime.h>

// Truncated path signature, D=6, depth K=4, L=65536 points (65535 increments).
// Output: [S1(6), S2(36), S3(216), S4(1296)] = 1554 floats.
//
// Stage A: 148 blocks x 144 threads. Each block runs 4 chunks of 111 steps
//          (36 threads per chunk, thread owns prefix ab = a*6+b: S2[ab],
//          S3[ab,*], S4[ab,*,*]), then tree-folds the 4 chunk signatures in
//          shared memory -> 148 signatures in g_sigA.
// Stage B: ownership-indexed parallel Chen tree: 148 -> 10 (merge1) -> 1
//          (merge2). Scratch globals are referenced ONLY in device code
//          (passing __device__ symbols as host-side kernel args is UB and was
//          the R10 failure).

#define DD 6
#define NINC 65535
#define NCHUNK 592
#define SPC 111                     // 592*111 = 65712 >= 65535, zero-padded
#define CPB 4
#define BLOCKS_A (NCHUNK / CPB)     // 148
#define THREADS_A (CPB * 36)        // 144
#define SIG 1554
#define O2 6
#define O3 42
#define O4 258
#define MERGE_THREADS 288           // 8 pair-merge groups of 36
#define G1 16                       // sigs per block, merge level 1
#define B1CNT ((BLOCKS_A + G1 - 1) / G1)   // 10

__device__ float g_sigA[BLOCKS_A * SIG];
__device__ float g_sigB[B1CNT * SIG];

// ---------------------------------------------------------------------------
// Pairwise Chen product, ownership-indexed: thread t = a*6+b owns
// C2[ab], C3[ab,*](6), C4[ab,*,*](36).  Compute phase reads A and B from
// shared into registers; write phase (after a block barrier) stores into A.
//   C_k = A_k + B_k + sum_{i=1}^{k-1} A_i (x) B_{k-i}
// ---------------------------------------------------------------------------
struct ChenRegs { float c1, c2, c3[6], c4[36]; };

__device__ __forceinline__ void chen_compute(
    const float* __restrict__ A, const float* __restrict__ B,
    int t, int a, int b, ChenRegs& r)
{
    float A1a  = A[a];
    float A2ab = A[O2 + t];
    float A3l[6], B1l[6];
#pragma unroll
    for (int c = 0; c < 6; c++) A3l[c] = A[O3 + t * 6 + c];
#pragma unroll
    for (int d = 0; d < 6; d++) B1l[d] = B[d];

    r.c1 = A1a + B[a];
    r.c2 = fmaf(A1a, B1l[b], A2ab + B[O2 + t]);

#pragma unroll
    for (int c = 0; c < 6; c++) {
        float v = A3l[c] + B[O3 + t * 6 + c];
        v = fmaf(A1a,  B[O2 + b * 6 + c], v);   // A1 (x) B2
        v = fmaf(A2ab, B1l[c],            v);   // A2 (x) B1
        r.c3[c] = v;
    }
#pragma unroll
    for (int k = 0; k < 36; k++) {              // k = c*6 + d
        float v = A[O4 + t * 36 + k] + B[O4 + t * 36 + k];
        v = fmaf(A2ab,        B[O2 + k],          v);   // A2 (x) B2
        v = fmaf(A1a,         B[O3 + b * 36 + k], v);   // A1 (x) B3
        v = fmaf(A3l[k / 6],  B1l[k % 6],         v);   // A3 (x) B1
        r.c4[k] = v;
    }
}

__device__ __forceinline__ void chen_write(
    float* __restrict__ A, int t, int a, int b, const ChenRegs& r)
{
    if (b == 0) A[a] = r.c1;
    A[O2 + t] = r.c2;
#pragma unroll
    for (int c = 0; c < 6; c++) A[O3 + t * 6 + c] = r.c3[c];
#pragma unroll
    for (int k = 0; k < 36; k++) A[O4 + t * 36 + k] = r.c4[k];
}

// Order-preserving in-place tree fold over cnt signatures in shared memory.
// Group g (36 threads) merges slot i = g*2s with slot i+s at level s.
// Chen is non-commutative; this pairing preserves left-to-right order.
__device__ __forceinline__ void tree_fold(float* sh, int cnt,
                                          int g, int t, int a, int b)
{
    for (int s = 1; s < cnt; s *= 2) {
        int i = g * 2 * s;
        bool act = (i + s) < cnt;
        ChenRegs r;
        if (act) chen_compute(sh + i * SIG, sh + (i + s) * SIG, t, a, b, r);
        __syncthreads();
        if (act) chen_write(sh + i * SIG, t, a, b, r);
        __syncthreads();
    }
}

// ---------------------------------------------------------------------------
// Stage A
// ---------------------------------------------------------------------------
__global__ __launch_bounds__(THREADS_A) void stageA_kernel(const float* __restrict__ x)
{
    // Reused buffer: increments (CPB*SPC*16 = 7104 floats), then 4 sigs (6216).
    __shared__ __align__(16) float sh[CPB * SPC * 16];

    const int tid = threadIdx.x;
    const long blkIncBase = (long)blockIdx.x * (CPB * SPC);

    for (int idx = tid; idx < CPB * SPC * DD; idx += THREADS_A) {
        int s = idx / DD;
        int j = idx - s * DD;
        long gidx = blkIncBase + s;
        float v = 0.0f;
        if (gidx < (long)NINC)
            v = x[(gidx + 1) * DD + j] - x[gidx * DD + j];
        sh[s * 16 + j]     = v;
        sh[s * 16 + 8 + j] = 0.5f * v;
    }
    __syncthreads();

    const int lc = tid / 36;
    const int ab = tid - lc * 36;
    const int a  = ab / 6;
    const int b  = ab - a * 6;

    float s1 = 0.0f, s2 = 0.0f;
    float s3[6], s4[36];
#pragma unroll
    for (int c = 0; c < 6; c++) s3[c] = 0.0f;
#pragma unroll
    for (int k = 0; k < 36; k++) s4[k] = 0.0f;

    const float* base = &sh[lc * SPC * 16];
    const float THIRD = 1.0f / 3.0f;

#pragma unroll 1
    for (int t = 0; t < SPC; t++) {
        const float* p = base + t * 16;
        const float4* q = (const float4*)p;
        float4 f0 = q[0], f1 = q[1], f2 = q[2], f3 = q[3];
        float vv[6] = { f0.x, f0.y, f0.z, f0.w, f1.x, f1.y };   // v
        float hv[6] = { f2.x, f2.y, f2.z, f2.w, f3.x, f3.y };   // v/2

        float vA = p[a],     vB = p[b];
        float hA = p[8 + a], hB = p[8 + b];
        float tA = vA * THIRD, tB = vB * THIRD;

        // Horner chains (all reads of s1,s2,s3 are pre-update values)
        float V1 = fmaf(vA, 0.25f, s1);
        float V2 = fmaf(V1, tB, s2);
        float W1 = s1 + tA;
        float W2 = fmaf(W1, hB, s2);
        float U1 = s1 + hA;
        s2 = fmaf(U1, vB, s2);
        s1 += vA;

#pragma unroll
        for (int c = 0; c < 6; c++) {
            float V3 = fmaf(V2, hv[c], s3[c]);     // uses old s3
            s3[c]    = fmaf(W2, vv[c], s3[c]);
#pragma unroll
            for (int d = 0; d < 6; d++)
                s4[c * 6 + d] = fmaf(V3, vv[d], s4[c * 6 + d]);
        }
    }

    // dump 4 chunk sigs into shared (reusing increment buffer), then fold
    __syncthreads();
    {
        float* o = sh + lc * SIG;
        if (b == 0) o[a] = s1;
        o[O2 + ab] = s2;
#pragma unroll
        for (int c = 0; c < 6; c++) o[O3 + ab * 6 + c] = s3[c];
#pragma unroll
        for (int k = 0; k < 36; k++) o[O4 + ab * 36 + k] = s4[k];
    }
    __syncthreads();

    tree_fold(sh, CPB, lc, ab, a, b);

    for (int k = tid; k < SIG; k += THREADS_A)
        g_sigA[(long)blockIdx.x * SIG + k] = sh[k];
}

// ---------------------------------------------------------------------------
// Stage B: parallel Chen tree. Globals referenced in DEVICE code only.
// ---------------------------------------------------------------------------
__global__ __launch_bounds__(MERGE_THREADS) void merge1_kernel()   // 148 -> 10
{
    extern __shared__ float sh[];
    const int tid = threadIdx.x;
    const int base = blockIdx.x * G1;
    int cnt = BLOCKS_A - base;
    if (cnt > G1) cnt = G1;

    for (int k = tid; k < cnt * SIG; k += MERGE_THREADS)
        sh[k] = g_sigA[(long)base * SIG + k];
    __syncthreads();

    const int g = tid / 36;
    const int t = tid - g * 36;
    const int a = t / 6;
    const int b = t - a * 6;

    tree_fold(sh, cnt, g, t, a, b);

    for (int k = tid; k < SIG; k += MERGE_THREADS)
        g_sigB[(long)blockIdx.x * SIG + k] = sh[k];
}

__global__ __launch_bounds__(MERGE_THREADS) void merge2_kernel(float* __restrict__ out)  // 10 -> 1
{
    extern __shared__ float sh[];
    const int tid = threadIdx.x;

    for (int k = tid; k < B1CNT * SIG; k += MERGE_THREADS)
        sh[k] = g_sigB[k];
    __syncthreads();

    const int g = tid / 36;
    const int t = tid - g * 36;
    const int a = t / 6;
    const int b = t - a * 6;

    tree_fold(sh, B1CNT, g, t, a, b);

    for (int k = tid; k < SIG; k += MERGE_THREADS)
        out[k] = sh[k];
}

// ---------------------------------------------------------------------------
extern "C" void kernel_launch(void* const* d_in, const int* in_sizes, int n_in,
                              void* d_out, int out_size)
{
    const float* x = (const float*)d_in[0];
    float* out = (float*)d_out;
    (void)in_sizes; (void)n_in; (void)out_size;

    // Opt in to >48KB dynamic smem (merge1: 16 sigs = 99456 B; merge2: 62160 B)
    static int attr_done = 0;
    if (!attr_done) {
        cudaFuncSetAttribute(merge1_kernel,
                             cudaFuncAttributeMaxDynamicSharedMemorySize,
                             G1 * SIG * (int)sizeof(float));
        cudaFuncSetAttribute(merge2_kernel,
                             cudaFuncAttributeMaxDynamicSharedMemorySize,
                             B1CNT * SIG * (int)sizeof(float));
        attr_done = 1;
    }

    stageA_kernel<<<BLOCKS_A, THREADS_A>>>(x);
    merge1_kernel<<<B1CNT, MERGE_THREADS, G1 * SIG * sizeof(float)>>>();
    merge2_kernel<<<1, MERGE_THREADS, B1CNT * SIG * sizeof(float)>>>(out);
}

// round 12
// speedup vs baseline: 2.9775x; 1.1383x over previous
#include <cuda_runtime.h>

// Truncated path signature, D=6, depth K=4, L=65536 points (65535 increments).
// Output: [S1(6), S2(36), S3(216), S4(1296)] = 1554 floats.
//
// Stage A: 148 blocks x 576 threads. Each block runs 16 chunks of 28 steps
//          (36 threads per chunk, thread owns prefix ab = a*6+b: S2[ab],
//          S3[ab,*], S4[ab,*,*]), then tree-folds the 16 chunk signatures in
//          (dynamic) shared memory -> 148 signatures in g_sigA.
//          R11 ran 4 chunks x 111 steps = 4.5 warps/SM and was issue-starved
//          (occ 7.8%, issue 26%); this rebalance gives 18 warps/SM.
// Stage B: ownership-indexed parallel Chen tree: 148 -> 10 -> 1 (two launches).

#define DD 6
#define NINC 65535
#define CPB 16
#define SPC 28                       // 148*16*28 = 66304 >= 65535, zero-padded
#define BLOCKS_A 148
#define THREADS_A (CPB * 36)         // 576
#define SIG 1554
#define O2 6
#define O3 42
#define O4 258
#define MERGE_THREADS 288            // 8 pair-merge groups of 36
#define G1 16                        // sigs per block, merge level 1
#define B1CNT ((BLOCKS_A + G1 - 1) / G1)   // 10

__device__ float g_sigA[BLOCKS_A * SIG];
__device__ float g_sigB[B1CNT * SIG];

// ---------------------------------------------------------------------------
// Pairwise Chen product, ownership-indexed: thread t = a*6+b owns
// C2[ab], C3[ab,*](6), C4[ab,*,*](36).  Compute phase reads A and B from
// shared into registers; write phase (after a block barrier) stores into A.
//   C_k = A_k + B_k + sum_{i=1}^{k-1} A_i (x) B_{k-i}
// ---------------------------------------------------------------------------
struct ChenRegs { float c1, c2, c3[6], c4[36]; };

__device__ __forceinline__ void chen_compute(
    const float* __restrict__ A, const float* __restrict__ B,
    int t, int a, int b, ChenRegs& r)
{
    float A1a  = A[a];
    float A2ab = A[O2 + t];
    float A3l[6], B1l[6];
#pragma unroll
    for (int c = 0; c < 6; c++) A3l[c] = A[O3 + t * 6 + c];
#pragma unroll
    for (int d = 0; d < 6; d++) B1l[d] = B[d];

    r.c1 = A1a + B[a];
    r.c2 = fmaf(A1a, B1l[b], A2ab + B[O2 + t]);

#pragma unroll
    for (int c = 0; c < 6; c++) {
        float v = A3l[c] + B[O3 + t * 6 + c];
        v = fmaf(A1a,  B[O2 + b * 6 + c], v);   // A1 (x) B2
        v = fmaf(A2ab, B1l[c],            v);   // A2 (x) B1
        r.c3[c] = v;
    }
#pragma unroll
    for (int k = 0; k < 36; k++) {              // k = c*6 + d
        float v = A[O4 + t * 36 + k] + B[O4 + t * 36 + k];
        v = fmaf(A2ab,        B[O2 + k],          v);   // A2 (x) B2
        v = fmaf(A1a,         B[O3 + b * 36 + k], v);   // A1 (x) B3
        v = fmaf(A3l[k / 6],  B1l[k % 6],         v);   // A3 (x) B1
        r.c4[k] = v;
    }
}

__device__ __forceinline__ void chen_write(
    float* __restrict__ A, int t, int a, int b, const ChenRegs& r)
{
    if (b == 0) A[a] = r.c1;
    A[O2 + t] = r.c2;
#pragma unroll
    for (int c = 0; c < 6; c++) A[O3 + t * 6 + c] = r.c3[c];
#pragma unroll
    for (int k = 0; k < 36; k++) A[O4 + t * 36 + k] = r.c4[k];
}

// Order-preserving in-place tree fold over cnt signatures in shared memory.
// Group g (36 threads) merges slot i = g*2s with slot i+s at level s.
// Chen is non-commutative; this pairing preserves left-to-right order.
__device__ __forceinline__ void tree_fold(float* sh, int cnt,
                                          int g, int t, int a, int b)
{
    for (int s = 1; s < cnt; s *= 2) {
        int i = g * 2 * s;
        bool act = (i + s) < cnt;
        ChenRegs r;
        if (act) chen_compute(sh + i * SIG, sh + (i + s) * SIG, t, a, b, r);
        __syncthreads();
        if (act) chen_write(sh + i * SIG, t, a, b, r);
        __syncthreads();
    }
}

// ---------------------------------------------------------------------------
// Stage A
// ---------------------------------------------------------------------------
__global__ __launch_bounds__(THREADS_A, 1) void stageA_kernel(const float* __restrict__ x)
{
    // Dynamic buffer reused: increments (CPB*SPC*16 = 7168 floats = 28KB),
    // then 16 chunk sigs (16*1554 = 24864 floats = 99.5KB).
    extern __shared__ __align__(16) float sh[];

    const int tid = threadIdx.x;
    const long blkIncBase = (long)blockIdx.x * (CPB * SPC);

    for (int idx = tid; idx < CPB * SPC * DD; idx += THREADS_A) {
        int s = idx / DD;
        int j = idx - s * DD;
        long gidx = blkIncBase + s;
        float v = 0.0f;
        if (gidx < (long)NINC)
            v = x[(gidx + 1) * DD + j] - x[gidx * DD + j];
        sh[s * 16 + j]     = v;
        sh[s * 16 + 8 + j] = 0.5f * v;
    }
    __syncthreads();

    const int lc = tid / 36;              // local chunk 0..15
    const int ab = tid - lc * 36;
    const int a  = ab / 6;
    const int b  = ab - a * 6;

    float s1 = 0.0f, s2 = 0.0f;
    float s3[6], s4[36];
#pragma unroll
    for (int c = 0; c < 6; c++) s3[c] = 0.0f;
#pragma unroll
    for (int k = 0; k < 36; k++) s4[k] = 0.0f;

    const float* base = &sh[lc * SPC * 16];
    const float THIRD = 1.0f / 3.0f;

#pragma unroll 1
    for (int t = 0; t < SPC; t++) {
        const float* p = base + t * 16;
        const float4* q = (const float4*)p;
        float4 f0 = q[0], f1 = q[1], f2 = q[2], f3 = q[3];
        float vv[6] = { f0.x, f0.y, f0.z, f0.w, f1.x, f1.y };   // v
        float hv[6] = { f2.x, f2.y, f2.z, f2.w, f3.x, f3.y };   // v/2

        float vA = p[a],     vB = p[b];
        float hA = p[8 + a], hB = p[8 + b];
        float tA = vA * THIRD, tB = vB * THIRD;

        // Horner chains (all reads of s1,s2,s3 are pre-update values)
        float V1 = fmaf(vA, 0.25f, s1);
        float V2 = fmaf(V1, tB, s2);
        float W1 = s1 + tA;
        float W2 = fmaf(W1, hB, s2);
        float U1 = s1 + hA;
        s2 = fmaf(U1, vB, s2);
        s1 += vA;

#pragma unroll
        for (int c = 0; c < 6; c++) {
            float V3 = fmaf(V2, hv[c], s3[c]);     // uses old s3
            s3[c]    = fmaf(W2, vv[c], s3[c]);
#pragma unroll
            for (int d = 0; d < 6; d++)
                s4[c * 6 + d] = fmaf(V3, vv[d], s4[c * 6 + d]);
        }
    }

    // dump 16 chunk sigs into shared (reusing increment buffer), then fold
    __syncthreads();
    {
        float* o = sh + lc * SIG;
        if (b == 0) o[a] = s1;
        o[O2 + ab] = s2;
#pragma unroll
        for (int c = 0; c < 6; c++) o[O3 + ab * 6 + c] = s3[c];
#pragma unroll
        for (int k = 0; k < 36; k++) o[O4 + ab * 36 + k] = s4[k];
    }
    __syncthreads();

    tree_fold(sh, CPB, lc, ab, a, b);

    for (int k = tid; k < SIG; k += THREADS_A)
        g_sigA[(long)blockIdx.x * SIG + k] = sh[k];
}

// ---------------------------------------------------------------------------
// Stage B: parallel Chen tree. Globals referenced in DEVICE code only.
// ---------------------------------------------------------------------------
__global__ __launch_bounds__(MERGE_THREADS) void merge1_kernel()   // 148 -> 10
{
    extern __shared__ float shm[];
    const int tid = threadIdx.x;
    const int base = blockIdx.x * G1;
    int cnt = BLOCKS_A - base;
    if (cnt > G1) cnt = G1;

    for (int k = tid; k < cnt * SIG; k += MERGE_THREADS)
        shm[k] = g_sigA[(long)base * SIG + k];
    __syncthreads();

    const int g = tid / 36;
    const int t = tid - g * 36;
    const int a = t / 6;
    const int b = t - a * 6;

    tree_fold(shm, cnt, g, t, a, b);

    for (int k = tid; k < SIG; k += MERGE_THREADS)
        g_sigB[(long)blockIdx.x * SIG + k] = shm[k];
}

__global__ __launch_bounds__(MERGE_THREADS) void merge2_kernel(float* __restrict__ out)  // 10 -> 1
{
    extern __shared__ float shm[];
    const int tid = threadIdx.x;

    for (int k = tid; k < B1CNT * SIG; k += MERGE_THREADS)
        shm[k] = g_sigB[k];
    __syncthreads();

    const int g = tid / 36;
    const int t = tid - g * 36;
    const int a = t / 6;
    const int b = t - a * 6;

    tree_fold(shm, B1CNT, g, t, a, b);

    for (int k = tid; k < SIG; k += MERGE_THREADS)
        out[k] = shm[k];
}

// ---------------------------------------------------------------------------
extern "C" void kernel_launch(void* const* d_in, const int* in_sizes, int n_in,
                              void* d_out, int out_size)
{
    const float* x = (const float*)d_in[0];
    float* out = (float*)d_out;
    (void)in_sizes; (void)n_in; (void)out_size;

    static int attr_done = 0;
    if (!attr_done) {
        cudaFuncSetAttribute(stageA_kernel,
                             cudaFuncAttributeMaxDynamicSharedMemorySize,
                             CPB * SIG * (int)sizeof(float));        // 99456 B
        cudaFuncSetAttribute(merge1_kernel,
                             cudaFuncAttributeMaxDynamicSharedMemorySize,
                             G1 * SIG * (int)sizeof(float));         // 99456 B
        cudaFuncSetAttribute(merge2_kernel,
                             cudaFuncAttributeMaxDynamicSharedMemorySize,
                             B1CNT * SIG * (int)sizeof(float));      // 62160 B
        attr_done = 1;
    }

    stageA_kernel<<<BLOCKS_A, THREADS_A, CPB * SIG * sizeof(float)>>>(x);
    merge1_kernel<<<B1CNT, MERGE_THREADS, G1 * SIG * sizeof(float)>>>();
    merge2_kernel<<<1, MERGE_THREADS, B1CNT * SIG * sizeof(float)>>>(out);
}

// round 13
// speedup vs baseline: 3.1656x; 1.0632x over previous
#include <cuda_runtime.h>

// Truncated path signature, D=6, depth K=4, L=65536 points (65535 increments).
// Output: [S1(6), S2(36), S3(216), S4(1296)] = 1554 floats.
//
// Single persistent kernel, 148 blocks x 576 threads (1 block/SM by regs;
// GB300 has 152 SMs so all blocks co-resident -> software grid barrier safe).
//   Phase 1: 16 chunks x 28 steps per block (36 threads/chunk, thread owns
//            prefix ab), in-block tree fold 16 -> 1, write to g_sigA.
//   Phase 2: blocks 0..9 tree-fold 16 sigs each: 148 -> 10 (g_sigB).
//   Phase 3: block 0 tree-folds 10 -> 1, writes d_out.
// Grid barriers: generation-counting atomic (no reset needed across graph
// replays: each barrier instance consumes exactly gridDim tickets).

#define DD 6
#define NINC 65535
#define CPB 16
#define SPC 28                       // 148*16*28 = 66304 >= 65535, zero-padded
#define BLOCKS_A 148
#define THREADS_A (CPB * 36)         // 576
#define SIG 1554
#define O2 6
#define O3 42
#define O4 258
#define G1 16
#define B1CNT ((BLOCKS_A + G1 - 1) / G1)   // 10

__device__ float g_sigA[BLOCKS_A * SIG];
__device__ float g_sigB[B1CNT * SIG];
__device__ unsigned int g_bar;       // zero-init; monotone across replays

__device__ __forceinline__ void grid_barrier()
{
    __syncthreads();
    if (threadIdx.x == 0) {
        __threadfence();                                   // release prior writes
        unsigned int ticket = atomicAdd(&g_bar, 1u);
        unsigned int target = (ticket / BLOCKS_A + 1u) * BLOCKS_A;
        unsigned int v;
        do {
            asm volatile("ld.acquire.gpu.u32 %0, [%1];" : "=r"(v) : "l"(&g_bar));
        } while (v < target);
    }
    __syncthreads();
}

// ---------------------------------------------------------------------------
// Pairwise Chen product, ownership-indexed: thread t = a*6+b owns
// C2[ab], C3[ab,*](6), C4[ab,*,*](36).
//   C_k = A_k + B_k + sum_{i=1}^{k-1} A_i (x) B_{k-i}   (A = left/earlier)
// ---------------------------------------------------------------------------
struct ChenRegs { float c1, c2, c3[6], c4[36]; };

__device__ __forceinline__ void chen_compute(
    const float* __restrict__ A, const float* __restrict__ B,
    int t, int a, int b, ChenRegs& r)
{
    float A1a  = A[a];
    float A2ab = A[O2 + t];
    float A3l[6], B1l[6];
#pragma unroll
    for (int c = 0; c < 6; c++) A3l[c] = A[O3 + t * 6 + c];
#pragma unroll
    for (int d = 0; d < 6; d++) B1l[d] = B[d];

    r.c1 = A1a + B[a];
    r.c2 = fmaf(A1a, B1l[b], A2ab + B[O2 + t]);

#pragma unroll
    for (int c = 0; c < 6; c++) {
        float v = A3l[c] + B[O3 + t * 6 + c];
        v = fmaf(A1a,  B[O2 + b * 6 + c], v);   // A1 (x) B2
        v = fmaf(A2ab, B1l[c],            v);   // A2 (x) B1
        r.c3[c] = v;
    }
#pragma unroll
    for (int k = 0; k < 36; k++) {              // k = c*6 + d
        float v = A[O4 + t * 36 + k] + B[O4 + t * 36 + k];
        v = fmaf(A2ab,        B[O2 + k],          v);   // A2 (x) B2
        v = fmaf(A1a,         B[O3 + b * 36 + k], v);   // A1 (x) B3
        v = fmaf(A3l[k / 6],  B1l[k % 6],         v);   // A3 (x) B1
        r.c4[k] = v;
    }
}

__device__ __forceinline__ void chen_write(
    float* __restrict__ A, int t, int a, int b, const ChenRegs& r)
{
    if (b == 0) A[a] = r.c1;
    A[O2 + t] = r.c2;
#pragma unroll
    for (int c = 0; c < 6; c++) A[O3 + t * 6 + c] = r.c3[c];
#pragma unroll
    for (int k = 0; k < 36; k++) A[O4 + t * 36 + k] = r.c4[k];
}

// Order-preserving in-place tree fold over cnt signatures in shared memory.
// Group g (36 threads) merges slot i = g*2s (left) with slot i+s (right).
// Requires #groups >= ceil(cnt/2).
__device__ __forceinline__ void tree_fold(float* sh, int cnt,
                                          int g, int t, int a, int b)
{
    for (int s = 1; s < cnt; s *= 2) {
        int i = g * 2 * s;
        bool act = (i + s) < cnt;
        ChenRegs r;
        if (act) chen_compute(sh + i * SIG, sh + (i + s) * SIG, t, a, b, r);
        __syncthreads();
        if (act) chen_write(sh + i * SIG, t, a, b, r);
        __syncthreads();
    }
}

// ---------------------------------------------------------------------------
__global__ __launch_bounds__(THREADS_A, 1) void sig_kernel(
    const float* __restrict__ x, float* __restrict__ out)
{
    // Dynamic smem reused: increments (CPB*SPC*8 = 3584 floats), then
    // 16 sigs (24864 floats = 99456 B).
    extern __shared__ __align__(16) float sh[];

    const int tid = threadIdx.x;
    const int g36 = tid / 36;             // chunk / merge group 0..15
    const int ab  = tid - g36 * 36;
    const int a   = ab / 6;
    const int b   = ab - a * 6;

    // ---- Phase 1: chunk signatures -------------------------------------
    {
        const long blkIncBase = (long)blockIdx.x * (CPB * SPC);
        for (int idx = tid; idx < CPB * SPC * DD; idx += THREADS_A) {
            int s = idx / DD;
            int j = idx - s * DD;
            long gidx = blkIncBase + s;
            float v = 0.0f;
            if (gidx < (long)NINC)
                v = x[(gidx + 1) * DD + j] - x[gidx * DD + j];
            sh[s * 8 + j] = v;
        }
        __syncthreads();

        float s1 = 0.0f, s2 = 0.0f;
        float s3[6], s4[36];
#pragma unroll
        for (int c = 0; c < 6; c++) s3[c] = 0.0f;
#pragma unroll
        for (int k = 0; k < 36; k++) s4[k] = 0.0f;

        const float* base = &sh[g36 * SPC * 8];
        const float THIRD = 1.0f / 3.0f;

#pragma unroll 1
        for (int t = 0; t < SPC; t++) {
            const float* p = base + t * 8;
            const float4* q = (const float4*)p;
            float4 f0 = q[0], f1 = q[1];
            float vv[6] = { f0.x, f0.y, f0.z, f0.w, f1.x, f1.y };

            float vA = p[a], vB = p[b];
            float tA = vA * THIRD, tB = vB * THIRD;

            // Horner chains (all reads of s1,s2,s3 are pre-update values)
            float V1 = fmaf(vA, 0.25f, s1);
            float V2 = fmaf(V1, tB, s2);
            float W1 = s1 + tA;
            float W2 = fmaf(W1, 0.5f * vB, s2);
            float U1 = fmaf(vA, 0.5f, s1);
            s2 = fmaf(U1, vB, s2);
            s1 += vA;
            float V2h = 0.5f * V2;

#pragma unroll
            for (int c = 0; c < 6; c++) {
                float V3 = fmaf(V2h, vv[c], s3[c]);    // uses old s3
                s3[c]    = fmaf(W2,  vv[c], s3[c]);
#pragma unroll
                for (int d = 0; d < 6; d++)
                    s4[c * 6 + d] = fmaf(V3, vv[d], s4[c * 6 + d]);
            }
        }

        __syncthreads();      // increments dead; reuse buffer for sigs
        {
            float* o = sh + g36 * SIG;
            if (b == 0) o[a] = s1;
            o[O2 + ab] = s2;
#pragma unroll
            for (int c = 0; c < 6; c++) o[O3 + ab * 6 + c] = s3[c];
#pragma unroll
            for (int k = 0; k < 36; k++) o[O4 + ab * 36 + k] = s4[k];
        }
        __syncthreads();

        tree_fold(sh, CPB, g36, ab, a, b);

        for (int k = tid; k < SIG; k += THREADS_A)
            g_sigA[(long)blockIdx.x * SIG + k] = sh[k];
    }

    grid_barrier();

    // ---- Phase 2: 148 -> 10 --------------------------------------------
    if (blockIdx.x < B1CNT) {
        const int base = blockIdx.x * G1;
        int cnt = BLOCKS_A - base;
        if (cnt > G1) cnt = G1;

        for (int k = tid; k < cnt * SIG; k += THREADS_A)
            sh[k] = g_sigA[(long)base * SIG + k];
        __syncthreads();

        tree_fold(sh, cnt, g36, ab, a, b);

        for (int k = tid; k < SIG; k += THREADS_A)
            g_sigB[(long)blockIdx.x * SIG + k] = sh[k];
    }

    grid_barrier();

    // ---- Phase 3: 10 -> 1 ------------------------------------------------
    if (blockIdx.x == 0) {
        for (int k = tid; k < B1CNT * SIG; k += THREADS_A)
            sh[k] = g_sigB[k];
        __syncthreads();

        tree_fold(sh, B1CNT, g36, ab, a, b);

        for (int k = tid; k < SIG; k += THREADS_A)
            out[k] = sh[k];
    }
}

// ---------------------------------------------------------------------------
extern "C" void kernel_launch(void* const* d_in, const int* in_sizes, int n_in,
                              void* d_out, int out_size)
{
    const float* x = (const float*)d_in[0];
    float* out = (float*)d_out;
    (void)in_sizes; (void)n_in; (void)out_size;

    const int smem = CPB * SIG * (int)sizeof(float);   // 99456 B
    cudaFuncSetAttribute(sig_kernel,
                         cudaFuncAttributeMaxDynamicSharedMemorySize, smem);

    sig_kernel<<<BLOCKS_A, THREADS_A, smem>>>(x, out);
}